// round 9
// baseline (speedup 1.0000x reference)
#include <cuda_runtime.h>
#include <cuda_bf16.h>

// Problem: B=64, L=1024, D=1280
//   pool_len = lengths + 2
//   emb[b,d]  = mean over l < pool_len of prev[b,l,d]
//   x         = relu(emb @ dense_w + dense_b)        [64,1280]
//   out       = x @ cls_w + cls_b                    [64,1]
//
// Four graph-captured kernels. Pool uses fine 16-row segments (4096 blocks,
// seg-major dispatch) so HW block scheduling load-balances ragged lengths.

#define Bq   64
#define Lq   1024
#define Dq   1280
#define D4   320             // float4 per row
#define NSEG 64              // pool segments per sequence
#define SEGR 16              // rows per pool segment

#define KS   4               // GEMM k-splits
#define KCH  320             // k per split
#define KC   64              // k staged per smem chunk
#define JT   16              // j tile
#define NJ   80              // Dq / JT

typedef unsigned long long u64;

// scratch (allocation-free: __device__ globals)
__device__ float g_part [Bq * NSEG * Dq];   // pool partials (21 MB, sparse use)
__device__ float g_emb  [Bq * Dq];          // pooled embedding
__device__ float g_xpart[KS * Bq * Dq];     // GEMM k-partials (1.31 MB)

// packed f32x2 FMA (SASS FFMA2): d = a*b + c per 32-bit lane
__device__ __forceinline__ u64 ffma2(u64 a, u64 b, u64 c) {
    u64 d;
    asm("fma.rn.f32x2 %0, %1, %2, %3;" : "=l"(d) : "l"(a), "l"(b), "l"(c));
    return d;
}

// ---------------------------------------------------------------------------
// Kernel 1: ragged pool partials. grid(B, NSEG) seg-major, 320 threads.
// Segment = 16 rows -> ~2100 active blocks over ~440 resident slots: the HW
// scheduler backfills as short blocks retire (ragged load balancing).
// ---------------------------------------------------------------------------
__global__ void __launch_bounds__(D4) pool_kernel(
    const float* __restrict__ prev, const int* __restrict__ lengths)
{
    const int b   = blockIdx.x;
    const int seg = blockIdx.y;
    const int tid = threadIdx.x;

    const int pl = lengths[b] + 2;            // pool_len in [2, 1023]
    const int l0 = seg * SEGR;
    const int n  = min(SEGR, pl - l0);        // rows this block must sum
    if (n <= 0) return;                       // reduce predicates identically

    float4 a0 = make_float4(0.f, 0.f, 0.f, 0.f);
    float4 a1 = a0, a2 = a0, a3 = a0;

    const float4* __restrict__ p =
        reinterpret_cast<const float4*>(prev) + ((size_t)b * Lq + l0) * D4 + tid;
    int l = 0;
    for (; l + 8 <= n; l += 8) {
        float4 v0 = p[(size_t)(l + 0) * D4];
        float4 v1 = p[(size_t)(l + 1) * D4];
        float4 v2 = p[(size_t)(l + 2) * D4];
        float4 v3 = p[(size_t)(l + 3) * D4];
        float4 v4 = p[(size_t)(l + 4) * D4];
        float4 v5 = p[(size_t)(l + 5) * D4];
        float4 v6 = p[(size_t)(l + 6) * D4];
        float4 v7 = p[(size_t)(l + 7) * D4];
        a0.x += v0.x; a0.y += v0.y; a0.z += v0.z; a0.w += v0.w;
        a1.x += v1.x; a1.y += v1.y; a1.z += v1.z; a1.w += v1.w;
        a2.x += v2.x; a2.y += v2.y; a2.z += v2.z; a2.w += v2.w;
        a3.x += v3.x; a3.y += v3.y; a3.z += v3.z; a3.w += v3.w;
        a0.x += v4.x; a0.y += v4.y; a0.z += v4.z; a0.w += v4.w;
        a1.x += v5.x; a1.y += v5.y; a1.z += v5.z; a1.w += v5.w;
        a2.x += v6.x; a2.y += v6.y; a2.z += v6.z; a2.w += v6.w;
        a3.x += v7.x; a3.y += v7.y; a3.z += v7.z; a3.w += v7.w;
    }
    for (; l < n; ++l) {
        float4 v = p[(size_t)l * D4];
        a0.x += v.x; a0.y += v.y; a0.z += v.z; a0.w += v.w;
    }

    float4 s;
    s.x = (a0.x + a1.x) + (a2.x + a3.x);
    s.y = (a0.y + a1.y) + (a2.y + a3.y);
    s.z = (a0.z + a1.z) + (a2.z + a3.z);
    s.w = (a0.w + a1.w) + (a2.w + a3.w);

    reinterpret_cast<float4*>(g_part)[((size_t)b * NSEG + seg) * D4 + tid] = s;
}

// ---------------------------------------------------------------------------
// Kernel 2: reduce valid partials + divide by pool_len. grid(B, 5), block 64.
// Only reads segments that pool_kernel actually wrote (same predicate).
// ---------------------------------------------------------------------------
__global__ void __launch_bounds__(64) reduce_kernel(const int* __restrict__ lengths)
{
    const int b   = blockIdx.x;
    const int tid = threadIdx.x;
    const int d4  = blockIdx.y * 64 + tid;              // 0..319
    const float4* gp = reinterpret_cast<const float4*>(g_part)
                       + (size_t)b * NSEG * D4 + d4;

    const int pl   = lengths[b] + 2;
    const int nseg = (pl + SEGR - 1) / SEGR;            // 1..64 valid segments

    float4 s0 = make_float4(0.f, 0.f, 0.f, 0.f);
    float4 s1 = s0, s2 = s0, s3 = s0;
    int seg = 0;
    for (; seg + 4 <= nseg; seg += 4) {
        float4 v0 = gp[(size_t)(seg + 0) * D4];
        float4 v1 = gp[(size_t)(seg + 1) * D4];
        float4 v2 = gp[(size_t)(seg + 2) * D4];
        float4 v3 = gp[(size_t)(seg + 3) * D4];
        s0.x += v0.x; s0.y += v0.y; s0.z += v0.z; s0.w += v0.w;
        s1.x += v1.x; s1.y += v1.y; s1.z += v1.z; s1.w += v1.w;
        s2.x += v2.x; s2.y += v2.y; s2.z += v2.z; s2.w += v2.w;
        s3.x += v3.x; s3.y += v3.y; s3.z += v3.z; s3.w += v3.w;
    }
    for (; seg < nseg; ++seg) {
        float4 v = gp[(size_t)seg * D4];
        s0.x += v.x; s0.y += v.y; s0.z += v.z; s0.w += v.w;
    }
    float4 s;
    s.x = (s0.x + s1.x) + (s2.x + s3.x);
    s.y = (s0.y + s1.y) + (s2.y + s3.y);
    s.z = (s0.z + s1.z) + (s2.z + s3.z);
    s.w = (s0.w + s1.w) + (s2.w + s3.w);

    const float inv = 1.0f / (float)pl;
    s.x *= inv; s.y *= inv; s.z *= inv; s.w *= inv;
    reinterpret_cast<float4*>(g_emb)[(size_t)b * D4 + d4] = s;
}

// ---------------------------------------------------------------------------
// Kernel 3: k-split GEMM with packed f32x2 FMA. grid(NJ=80, KS=4), 256 thr.
// Block tile: 64 b x 16 j x 320 k. Thread: 4 b x 1 j (2 u64 accumulators).
// W staged pre-duplicated into both f32x2 lanes -> inner loop is
// 1 LDS.128 + 1 LDS.64 + 2 FFMA2 per 8 FMA.
// ---------------------------------------------------------------------------
__global__ void __launch_bounds__(256) gemm_kernel(const float* __restrict__ W)
{
    __shared__ __align__(16) float sE[KC][68];   // emb^T chunk (16B-aligned rows)
    __shared__ __align__(16) u64   sWp[KC][JT];  // W duplicated into both lanes

    const int tid = threadIdx.x;
    const int j0  = blockIdx.x * JT;
    const int k0  = blockIdx.y * KCH;
    const int bq  = tid >> 4;        // 0..15 -> rows 4bq..4bq+3
    const int j   = tid & 15;        // 0..15

    u64 acc01 = 0ull, acc23 = 0ull;  // f32x2 zeros

    for (int c = 0; c < KCH; c += KC) {
        __syncthreads();
        // stage emb^T: consecutive tid -> consecutive kk (coalesced gmem read)
        for (int i = tid; i < KC * Bq; i += 256) {
            int kk = i & (KC - 1);
            int b  = i >> 6;
            sE[kk][b] = g_emb[(size_t)b * Dq + k0 + c + kk];
        }
        // stage W, duplicating each scalar into both f32x2 lanes
        for (int i = tid; i < KC * JT; i += 256) {
            int kk = i >> 4;
            int jj = i & 15;
            float w = W[(size_t)(k0 + c + kk) * Dq + j0 + jj];
            float2 t = make_float2(w, w);
            sWp[kk][jj] = *reinterpret_cast<u64*>(&t);
        }
        __syncthreads();

#pragma unroll 16
        for (int kk = 0; kk < KC; ++kk) {
            const u64* erow = reinterpret_cast<const u64*>(&sE[kk][0]);
            u64 e01 = erow[2 * bq];
            u64 e23 = erow[2 * bq + 1];
            u64 w   = sWp[kk][j];
            acc01 = ffma2(e01, w, acc01);
            acc23 = ffma2(e23, w, acc23);
        }
    }

    float2 r01 = *reinterpret_cast<float2*>(&acc01);
    float2 r23 = *reinterpret_cast<float2*>(&acc23);
    float* dst = &g_xpart[((size_t)blockIdx.y * Bq + 4 * bq) * Dq + j0 + j];
    dst[0]      = r01.x;
    dst[Dq]     = r01.y;
    dst[2 * Dq] = r23.x;
    dst[3 * Dq] = r23.y;
}

// ---------------------------------------------------------------------------
// Kernel 4: reduce k-partials, +bias, relu, dot cls_w, +cls_b. grid(B), 320.
// Direct store, no atomics, deterministic.
// ---------------------------------------------------------------------------
__global__ void __launch_bounds__(D4) final_kernel(
    const float* __restrict__ dense_b,
    const float* __restrict__ cls_w,
    const float* __restrict__ cls_b,
    float* __restrict__ out)
{
    const int b   = blockIdx.x;
    const int tid = threadIdx.x;
    const float4* xp = reinterpret_cast<const float4*>(g_xpart);

    float4 s = reinterpret_cast<const float4*>(dense_b)[tid];
#pragma unroll
    for (int ks = 0; ks < KS; ++ks) {
        float4 v = xp[((size_t)ks * Bq + b) * D4 + tid];
        s.x += v.x; s.y += v.y; s.z += v.z; s.w += v.w;
    }
    s.x = fmaxf(s.x, 0.f); s.y = fmaxf(s.y, 0.f);
    s.z = fmaxf(s.z, 0.f); s.w = fmaxf(s.w, 0.f);

    float4 w = reinterpret_cast<const float4*>(cls_w)[tid];
    float part = s.x * w.x + s.y * w.y + s.z * w.z + s.w * w.w;

    __shared__ float red[10];
#pragma unroll
    for (int o = 16; o > 0; o >>= 1)
        part += __shfl_down_sync(0xffffffffu, part, o);
    if ((tid & 31) == 0) red[tid >> 5] = part;
    __syncthreads();
    if (tid == 0) {
        float tot = 0.f;
#pragma unroll
        for (int i = 0; i < 10; ++i) tot += red[i];
        out[b] = tot + cls_b[0];
    }
}

// ---------------------------------------------------------------------------
extern "C" void kernel_launch(void* const* d_in, const int* in_sizes, int n_in,
                              void* d_out, int out_size)
{
    const float* prev    = (const float*)d_in[0];
    const int*   lengths = (const int*)  d_in[1];
    const float* dense_w = (const float*)d_in[2];
    const float* dense_b = (const float*)d_in[3];
    const float* cls_w   = (const float*)d_in[4];
    const float* cls_b   = (const float*)d_in[5];
    float*       out     = (float*)d_out;

    pool_kernel  <<<dim3(Bq, NSEG), D4>>>(prev, lengths);
    reduce_kernel<<<dim3(Bq, 5), 64>>>(lengths);
    gemm_kernel  <<<dim3(NJ, KS), 256>>>(dense_w);
    final_kernel <<<Bq, D4>>>(dense_b, cls_w, cls_b, out);
}

// round 10
// speedup vs baseline: 1.3039x; 1.3039x over previous
#include <cuda_runtime.h>
#include <cuda_bf16.h>

// Problem: B=64, L=1024, D=1280
//   pool_len = lengths + 2
//   emb[b,d]  = mean over l < pool_len of prev[b,l,d]
//   x         = relu(emb @ dense_w + dense_b)        [64,1280]
//   out       = x @ cls_w + cls_b                    [64,1]
//
// Two launches:
//   1) pool_kernel  — grid(64,16), 320 thr, SEGR=64 (proven best config)
//   2) epilogue_kernel — 320 blocks x 256 thr, ALL co-resident (3/SM x 148),
//      reduce -> grid barrier -> k-split GEMM -> grid barrier -> final.

#define Bq   64
#define Lq   1024
#define Dq   1280
#define D4   320             // float4 per row
#define NSEG 16
#define SEGR 64              // rows per pool segment

#define KS   4               // GEMM k-splits
#define KCH  320             // k per split
#define KC   64              // k staged per smem chunk
#define JT   16              // j tile
#define NJ   80              // Dq / JT

#define NB2  320             // epilogue blocks (<= 148*3 resident)

typedef unsigned long long u64;

// scratch (allocation-free: __device__ globals)
__device__ float g_part [Bq * NSEG * Dq];   // pool partials (5.24 MB)
__device__ float g_emb  [Bq * Dq];          // pooled embedding
__device__ float g_xpart[KS * Bq * Dq];     // GEMM k-partials (1.31 MB)

// barrier state: count returns to 0 each use; phase grows monotonically
// (replay-safe: no reset needed across graph replays)
__device__ unsigned g_bar_count = 0;
__device__ unsigned g_bar_phase = 0;

// packed f32x2 FMA (SASS FFMA2): per-lane d = a*b + c
__device__ __forceinline__ u64 ffma2(u64 a, u64 b, u64 c) {
    u64 d;
    asm("fma.rn.f32x2 %0, %1, %2, %3;" : "=l"(d) : "l"(a), "l"(b), "l"(c));
    return d;
}

__device__ __forceinline__ void grid_barrier()
{
    __syncthreads();
    if (threadIdx.x == 0) {
        __threadfence();
        unsigned ph = *(volatile unsigned*)&g_bar_phase;
        __threadfence();
        if (atomicAdd(&g_bar_count, 1u) == NB2 - 1u) {
            *(volatile unsigned*)&g_bar_count = 0u;
            __threadfence();
            atomicAdd(&g_bar_phase, 1u);     // release
        } else {
            while (*(volatile unsigned*)&g_bar_phase == ph) __nanosleep(64);
        }
        __threadfence();
    }
    __syncthreads();
}

// ---------------------------------------------------------------------------
// Kernel 1: ragged partial pool (round-6 proven config).
// grid(B, NSEG=16), 320 threads, 64-row segments, MLP=8.
// ---------------------------------------------------------------------------
__global__ void __launch_bounds__(D4) pool_kernel(
    const float* __restrict__ prev, const int* __restrict__ lengths)
{
    const int b   = blockIdx.x;
    const int seg = blockIdx.y;
    const int tid = threadIdx.x;

    const int pl = lengths[b] + 2;            // pool_len in [2, 1023]
    const int l0 = seg * SEGR;
    const int n  = min(SEGR, pl - l0);

    float4 a0 = make_float4(0.f, 0.f, 0.f, 0.f);
    float4 a1 = a0, a2 = a0, a3 = a0;

    if (n > 0) {
        const float4* __restrict__ p =
            reinterpret_cast<const float4*>(prev) + ((size_t)b * Lq + l0) * D4 + tid;
        int l = 0;
        for (; l + 8 <= n; l += 8) {
            float4 v0 = p[(size_t)(l + 0) * D4];
            float4 v1 = p[(size_t)(l + 1) * D4];
            float4 v2 = p[(size_t)(l + 2) * D4];
            float4 v3 = p[(size_t)(l + 3) * D4];
            float4 v4 = p[(size_t)(l + 4) * D4];
            float4 v5 = p[(size_t)(l + 5) * D4];
            float4 v6 = p[(size_t)(l + 6) * D4];
            float4 v7 = p[(size_t)(l + 7) * D4];
            a0.x += v0.x; a0.y += v0.y; a0.z += v0.z; a0.w += v0.w;
            a1.x += v1.x; a1.y += v1.y; a1.z += v1.z; a1.w += v1.w;
            a2.x += v2.x; a2.y += v2.y; a2.z += v2.z; a2.w += v2.w;
            a3.x += v3.x; a3.y += v3.y; a3.z += v3.z; a3.w += v3.w;
            a0.x += v4.x; a0.y += v4.y; a0.z += v4.z; a0.w += v4.w;
            a1.x += v5.x; a1.y += v5.y; a1.z += v5.z; a1.w += v5.w;
            a2.x += v6.x; a2.y += v6.y; a2.z += v6.z; a2.w += v6.w;
            a3.x += v7.x; a3.y += v7.y; a3.z += v7.z; a3.w += v7.w;
        }
        for (; l < n; ++l) {
            float4 v = p[(size_t)l * D4];
            a0.x += v.x; a0.y += v.y; a0.z += v.z; a0.w += v.w;
        }
    }
    float4 s;
    s.x = (a0.x + a1.x) + (a2.x + a3.x);
    s.y = (a0.y + a1.y) + (a2.y + a3.y);
    s.z = (a0.z + a1.z) + (a2.z + a3.z);
    s.w = (a0.w + a1.w) + (a2.w + a3.w);
    reinterpret_cast<float4*>(g_part)[((size_t)b * NSEG + seg) * D4 + tid] = s;
}

// ---------------------------------------------------------------------------
// Kernel 2: fused epilogue. 320 blocks x 256 threads, all co-resident.
// ---------------------------------------------------------------------------
__global__ void __launch_bounds__(256, 3) epilogue_kernel(
    const int*   __restrict__ lengths,
    const float* __restrict__ W,
    const float* __restrict__ dense_b,
    const float* __restrict__ cls_w,
    const float* __restrict__ cls_b,
    float*       __restrict__ out)
{
    __shared__ __align__(16) float sE[KC][68];   // emb^T chunk (17.4 KB)
    __shared__ __align__(16) u64   sWp[KC][JT];  // W dup'd lanes  (8 KB)
    __shared__ float red[8];

    const int bid = blockIdx.x;
    const int tid = threadIdx.x;

    // ---- Phase R: reduce pool partials + scale. 320 tasks = 64 b x 5 slices.
    {
        const int b  = bid & 63;
        const int sl = bid >> 6;                 // 0..4
        if (tid < 64) {
            const int d4 = sl * 64 + tid;        // 0..319
            const float4* gp = reinterpret_cast<const float4*>(g_part)
                               + (size_t)b * NSEG * D4 + d4;
            float4 s0 = make_float4(0.f, 0.f, 0.f, 0.f);
            float4 s1 = s0, s2 = s0, s3 = s0;
#pragma unroll
            for (int seg = 0; seg < NSEG; seg += 4) {
                float4 v0 = gp[(size_t)(seg + 0) * D4];
                float4 v1 = gp[(size_t)(seg + 1) * D4];
                float4 v2 = gp[(size_t)(seg + 2) * D4];
                float4 v3 = gp[(size_t)(seg + 3) * D4];
                s0.x += v0.x; s0.y += v0.y; s0.z += v0.z; s0.w += v0.w;
                s1.x += v1.x; s1.y += v1.y; s1.z += v1.z; s1.w += v1.w;
                s2.x += v2.x; s2.y += v2.y; s2.z += v2.z; s2.w += v2.w;
                s3.x += v3.x; s3.y += v3.y; s3.z += v3.z; s3.w += v3.w;
            }
            float4 s;
            s.x = (s0.x + s1.x) + (s2.x + s3.x);
            s.y = (s0.y + s1.y) + (s2.y + s3.y);
            s.z = (s0.z + s1.z) + (s2.z + s3.z);
            s.w = (s0.w + s1.w) + (s2.w + s3.w);
            const float inv = 1.0f / (float)(lengths[b] + 2);
            s.x *= inv; s.y *= inv; s.z *= inv; s.w *= inv;
            reinterpret_cast<float4*>(g_emb)[(size_t)b * D4 + d4] = s;
        }
    }

    grid_barrier();

    // ---- Phase G: k-split GEMM, one (ky, jx) tile per block.
    {
        const int ky = bid / NJ;                 // 0..3
        const int jx = bid % NJ;                 // 0..79
        const int j0 = jx * JT;
        const int k0 = ky * KCH;
        const int bq = tid >> 4;                 // 0..15 -> rows 4bq..4bq+3
        const int j  = tid & 15;

        u64 acc01 = 0ull, acc23 = 0ull;

        for (int c = 0; c < KCH; c += KC) {
            __syncthreads();
            for (int i = tid; i < KC * Bq; i += 256) {
                int kk = i & (KC - 1);
                int b  = i >> 6;
                sE[kk][b] = g_emb[(size_t)b * Dq + k0 + c + kk];
            }
            for (int i = tid; i < KC * JT; i += 256) {
                int kk = i >> 4;
                int jj = i & 15;
                float w = W[(size_t)(k0 + c + kk) * Dq + j0 + jj];
                float2 t = make_float2(w, w);
                sWp[kk][jj] = *reinterpret_cast<u64*>(&t);
            }
            __syncthreads();

#pragma unroll 16
            for (int kk = 0; kk < KC; ++kk) {
                const u64* erow = reinterpret_cast<const u64*>(&sE[kk][0]);
                u64 e01 = erow[2 * bq];
                u64 e23 = erow[2 * bq + 1];
                u64 w   = sWp[kk][j];
                acc01 = ffma2(e01, w, acc01);
                acc23 = ffma2(e23, w, acc23);
            }
        }

        float2 r01 = *reinterpret_cast<float2*>(&acc01);
        float2 r23 = *reinterpret_cast<float2*>(&acc23);
        float* dst = &g_xpart[((size_t)ky * Bq + 4 * bq) * Dq + j0 + j];
        dst[0]      = r01.x;
        dst[Dq]     = r01.y;
        dst[2 * Dq] = r23.x;
        dst[3 * Dq] = r23.y;
    }

    grid_barrier();

    // ---- Phase F: final. First 64 blocks, one per b. Direct store.
    if (bid < Bq) {
        const int b = bid;
        const float4* xp = reinterpret_cast<const float4*>(g_xpart);

        float part = 0.f;
#pragma unroll
        for (int rep = 0; rep < 2; ++rep) {
            int d4 = rep * 256 + tid;            // 0..255, 256..319
            if (d4 < D4) {
                float4 s = reinterpret_cast<const float4*>(dense_b)[d4];
#pragma unroll
                for (int ks = 0; ks < KS; ++ks) {
                    float4 v = xp[((size_t)ks * Bq + b) * D4 + d4];
                    s.x += v.x; s.y += v.y; s.z += v.z; s.w += v.w;
                }
                s.x = fmaxf(s.x, 0.f); s.y = fmaxf(s.y, 0.f);
                s.z = fmaxf(s.z, 0.f); s.w = fmaxf(s.w, 0.f);
                float4 w = reinterpret_cast<const float4*>(cls_w)[d4];
                part += s.x * w.x + s.y * w.y + s.z * w.z + s.w * w.w;
            }
        }
#pragma unroll
        for (int o = 16; o > 0; o >>= 1)
            part += __shfl_down_sync(0xffffffffu, part, o);
        if ((tid & 31) == 0) red[tid >> 5] = part;
        __syncthreads();
        if (tid == 0) {
            float tot = 0.f;
#pragma unroll
            for (int i = 0; i < 8; ++i) tot += red[i];
            out[b] = tot + cls_b[0];
        }
    }
}

// ---------------------------------------------------------------------------
extern "C" void kernel_launch(void* const* d_in, const int* in_sizes, int n_in,
                              void* d_out, int out_size)
{
    const float* prev    = (const float*)d_in[0];
    const int*   lengths = (const int*)  d_in[1];
    const float* dense_w = (const float*)d_in[2];
    const float* dense_b = (const float*)d_in[3];
    const float* cls_w   = (const float*)d_in[4];
    const float* cls_b   = (const float*)d_in[5];
    float*       out     = (float*)d_out;

    pool_kernel    <<<dim3(Bq, NSEG), D4>>>(prev, lengths);
    epilogue_kernel<<<NB2, 256>>>(lengths, dense_w, dense_b, cls_w, cls_b, out);
}

// round 11
// speedup vs baseline: 1.3695x; 1.0503x over previous
#include <cuda_runtime.h>
#include <cuda_bf16.h>

// Problem: B=64, L=1024, D=1280
//   pool_len = lengths + 2
//   emb[b,d]  = mean over l < pool_len of prev[b,l,d]
//   x         = relu(emb @ dense_w + dense_b)        [64,1280]
//   out       = x @ cls_w + cls_b                    [64,1]
//
// Three launches:
//  1) pool_kernel : 592 blocks x 320 thr. Exact task list over valid 64-row
//     segments (prefix sum of ceil(pool_len/64)) -> zero empty blocks, near-
//     perfect ragged balance. Last-arriving block per b reduces partials and
//     writes embT[k][b] (fused reduce; monotonic counters, replay-safe).
//  2) gemm_kernel : 320 blocks x 128 thr. Tile 64b x 64j x 80k, thread
//     2b x 16j, FFMA2 inner loop (16 FFMA2 per 5 LDS).
//  3) final_kernel: 64 blocks x 320 thr. k-partial reduce + bias + relu +
//     cls dot, direct store.

#define Bq    64
#define Lq    1024
#define Dq    1280
#define D4    320            // float4 per row
#define SEGR  64             // rows per pool segment
#define MAXSEG 16            // max segments per sequence

#define GPOOL 592            // pool blocks (4 per SM x 148)

#define KS    16             // GEMM k-splits
#define KCH   80             // k per split
#define NJ    20             // j tiles of 64
#define JTW   64             // j tile width

typedef unsigned long long u64;

// scratch (allocation-free: __device__ globals)
__device__ float    g_part [Bq * MAXSEG * Dq];  // pool partials (5.24 MB)
__device__ float    g_embT [Dq * Bq];           // emb transposed [k][b]
__device__ float    g_xpart[KS * Bq * Dq];      // GEMM k-partials (5.24 MB)
__device__ unsigned g_cnt  [Bq];                // arrival counters (monotonic)

// packed f32x2 FMA (SASS FFMA2): per-lane d = a*b + c
__device__ __forceinline__ u64 ffma2(u64 a, u64 b, u64 c) {
    u64 d;
    asm("fma.rn.f32x2 %0, %1, %2, %3;" : "=l"(d) : "l"(a), "l"(b), "l"(c));
    return d;
}
__device__ __forceinline__ u64 pack2(float lo, float hi) {
    u64 d;
    asm("mov.b64 %0, {%1, %2};" : "=l"(d) : "f"(lo), "f"(hi));
    return d;
}
__device__ __forceinline__ void unpack2(u64 v, float& lo, float& hi) {
    asm("mov.b64 {%0, %1}, %2;" : "=f"(lo), "=f"(hi) : "l"(v));
}

// ---------------------------------------------------------------------------
// Kernel 1: balanced ragged pool + fused per-b reduction.
// ---------------------------------------------------------------------------
__global__ void __launch_bounds__(D4) pool_kernel(
    const float* __restrict__ prev, const int* __restrict__ lengths)
{
    __shared__ int s_pre[Bq + 1];
    __shared__ int s_last;

    const int tid = threadIdx.x;
    const int bid = blockIdx.x;

    if (tid == 0) {
        int acc = 0;
        s_pre[0] = 0;
        for (int b = 0; b < Bq; ++b) {
            int pl = lengths[b] + 2;
            acc += (pl + SEGR - 1) >> 6;          // ceil(pl/64)
            s_pre[b + 1] = acc;
        }
    }
    __syncthreads();
    const int S = s_pre[Bq];                      // total valid segments

    for (int t = bid; t < S; t += GPOOL) {
        // binary search: b with s_pre[b] <= t < s_pre[b+1]
        int lo = 0, hi = Bq;
        while (hi - lo > 1) {
            int m = (lo + hi) >> 1;
            if (s_pre[m] <= t) lo = m; else hi = m;
        }
        const int b    = lo;
        const int seg  = t - s_pre[b];
        const int pl   = lengths[b] + 2;
        const int l0   = seg * SEGR;
        const int n    = min(SEGR, pl - l0);      // >= 1 by construction
        const int nseg = s_pre[b + 1] - s_pre[b];

        float4 a0 = make_float4(0.f, 0.f, 0.f, 0.f);
        float4 a1 = a0, a2 = a0, a3 = a0;

        const float4* __restrict__ p =
            reinterpret_cast<const float4*>(prev) + ((size_t)b * Lq + l0) * D4 + tid;
        int l = 0;
        for (; l + 8 <= n; l += 8) {
            float4 v0 = p[(size_t)(l + 0) * D4];
            float4 v1 = p[(size_t)(l + 1) * D4];
            float4 v2 = p[(size_t)(l + 2) * D4];
            float4 v3 = p[(size_t)(l + 3) * D4];
            float4 v4 = p[(size_t)(l + 4) * D4];
            float4 v5 = p[(size_t)(l + 5) * D4];
            float4 v6 = p[(size_t)(l + 6) * D4];
            float4 v7 = p[(size_t)(l + 7) * D4];
            a0.x += v0.x; a0.y += v0.y; a0.z += v0.z; a0.w += v0.w;
            a1.x += v1.x; a1.y += v1.y; a1.z += v1.z; a1.w += v1.w;
            a2.x += v2.x; a2.y += v2.y; a2.z += v2.z; a2.w += v2.w;
            a3.x += v3.x; a3.y += v3.y; a3.z += v3.z; a3.w += v3.w;
            a0.x += v4.x; a0.y += v4.y; a0.z += v4.z; a0.w += v4.w;
            a1.x += v5.x; a1.y += v5.y; a1.z += v5.z; a1.w += v5.w;
            a2.x += v6.x; a2.y += v6.y; a2.z += v6.z; a2.w += v6.w;
            a3.x += v7.x; a3.y += v7.y; a3.z += v7.z; a3.w += v7.w;
        }
        for (; l < n; ++l) {
            float4 v = p[(size_t)l * D4];
            a0.x += v.x; a0.y += v.y; a0.z += v.z; a0.w += v.w;
        }
        float4 s;
        s.x = (a0.x + a1.x) + (a2.x + a3.x);
        s.y = (a0.y + a1.y) + (a2.y + a3.y);
        s.z = (a0.z + a1.z) + (a2.z + a3.z);
        s.w = (a0.w + a1.w) + (a2.w + a3.w);
        reinterpret_cast<float4*>(g_part)[((size_t)b * MAXSEG + seg) * D4 + tid] = s;

        // publish partial, count arrival; last arrival reduces this b
        __threadfence();
        __syncthreads();
        if (tid == 0) {
            unsigned old = atomicAdd(&g_cnt[b], 1u);
            s_last = (((old + 1u) % (unsigned)nseg) == 0u) ? 1 : 0;
        }
        __syncthreads();
        if (s_last) {
            __threadfence();   // acquire other blocks' partials
            const float4* gp = reinterpret_cast<const float4*>(g_part)
                               + (size_t)b * MAXSEG * D4 + tid;
            float4 r = make_float4(0.f, 0.f, 0.f, 0.f);
            for (int sg = 0; sg < nseg; ++sg) {
                float4 v = gp[(size_t)sg * D4];
                r.x += v.x; r.y += v.y; r.z += v.z; r.w += v.w;
            }
            const float inv = 1.0f / (float)pl;
            r.x *= inv; r.y *= inv; r.z *= inv; r.w *= inv;
            // write transposed: embT[k][b], k = 4*tid..4*tid+3
            g_embT[(size_t)(4 * tid + 0) * Bq + b] = r.x;
            g_embT[(size_t)(4 * tid + 1) * Bq + b] = r.y;
            g_embT[(size_t)(4 * tid + 2) * Bq + b] = r.z;
            g_embT[(size_t)(4 * tid + 3) * Bq + b] = r.w;
        }
        __syncthreads();       // protect s_last across task iterations
    }
}

// ---------------------------------------------------------------------------
// Kernel 2: k-split GEMM, high-intensity FFMA2.
// grid 320 = (ky 0..15) * 20 + jx. Block tile 64b x 64j x 80k, 128 threads.
// Thread tile: 2b x 16j -> 16 u64 accumulators (j-pairs).
// ---------------------------------------------------------------------------
__global__ void __launch_bounds__(128) gemm_kernel(const float* __restrict__ W)
{
    __shared__ __align__(16) float sE[KCH][Bq];    // embT chunk  20 KB
    __shared__ __align__(16) float sW[KCH][JTW];   // W tile      20 KB

    const int tid = threadIdx.x;
    const int ky  = blockIdx.x / NJ;               // 0..15
    const int jx  = blockIdx.x % NJ;               // 0..19
    const int k0  = ky * KCH;
    const int j0  = jx * JTW;
    const int bg  = tid >> 2;                      // 0..31 -> b = 2bg, 2bg+1
    const int jg  = tid & 3;                       // 0..3  -> j = 16jg..16jg+15

    // stage embT chunk (coalesced: consecutive tid -> consecutive b)
    for (int i = tid; i < KCH * Bq; i += 128) {
        int kk = i >> 6;
        int b  = i & 63;
        sE[kk][b] = g_embT[(size_t)(k0 + kk) * Bq + b];
    }
    // stage W tile (coalesced rows of 64 floats)
    for (int i = tid; i < KCH * JTW; i += 128) {
        int kk = i >> 6;
        int jj = i & 63;
        sW[kk][jj] = W[(size_t)(k0 + kk) * Dq + j0 + jj];
    }
    __syncthreads();

    u64 acc0[8], acc1[8];
#pragma unroll
    for (int pIdx = 0; pIdx < 8; ++pIdx) { acc0[pIdx] = 0ull; acc1[pIdx] = 0ull; }

#pragma unroll 8
    for (int kk = 0; kk < KCH; ++kk) {
        float2 e = *reinterpret_cast<const float2*>(&sE[kk][2 * bg]);
        u64 e0 = pack2(e.x, e.x);
        u64 e1 = pack2(e.y, e.y);
        float4 w0 = *reinterpret_cast<const float4*>(&sW[kk][16 * jg + 0]);
        float4 w1 = *reinterpret_cast<const float4*>(&sW[kk][16 * jg + 4]);
        float4 w2 = *reinterpret_cast<const float4*>(&sW[kk][16 * jg + 8]);
        float4 w3 = *reinterpret_cast<const float4*>(&sW[kk][16 * jg + 12]);
        u64 wp[8];
        wp[0] = pack2(w0.x, w0.y); wp[1] = pack2(w0.z, w0.w);
        wp[2] = pack2(w1.x, w1.y); wp[3] = pack2(w1.z, w1.w);
        wp[4] = pack2(w2.x, w2.y); wp[5] = pack2(w2.z, w2.w);
        wp[6] = pack2(w3.x, w3.y); wp[7] = pack2(w3.z, w3.w);
#pragma unroll
        for (int pIdx = 0; pIdx < 8; ++pIdx) {
            acc0[pIdx] = ffma2(e0, wp[pIdx], acc0[pIdx]);
            acc1[pIdx] = ffma2(e1, wp[pIdx], acc1[pIdx]);
        }
    }

    // write 2 rows x 16 j (consecutive j -> 4 float4 per row)
    const int b0 = 2 * bg;
    float* dst0 = &g_xpart[((size_t)ky * Bq + b0) * Dq + j0 + 16 * jg];
    float* dst1 = dst0 + Dq;
#pragma unroll
    for (int q = 0; q < 4; ++q) {
        float x0, y0, z0, w0f, x1, y1, z1, w1f;
        unpack2(acc0[2 * q],     x0, y0);
        unpack2(acc0[2 * q + 1], z0, w0f);
        unpack2(acc1[2 * q],     x1, y1);
        unpack2(acc1[2 * q + 1], z1, w1f);
        reinterpret_cast<float4*>(dst0)[q] = make_float4(x0, y0, z0, w0f);
        reinterpret_cast<float4*>(dst1)[q] = make_float4(x1, y1, z1, w1f);
    }
}

// ---------------------------------------------------------------------------
// Kernel 3: reduce k-partials, +bias, relu, dot cls_w, +cls_b. grid(64), 320.
// ---------------------------------------------------------------------------
__global__ void __launch_bounds__(D4) final_kernel(
    const float* __restrict__ dense_b,
    const float* __restrict__ cls_w,
    const float* __restrict__ cls_b,
    float* __restrict__ out)
{
    const int b   = blockIdx.x;
    const int tid = threadIdx.x;
    const float4* xp = reinterpret_cast<const float4*>(g_xpart);

    float4 s = reinterpret_cast<const float4*>(dense_b)[tid];
#pragma unroll
    for (int ks = 0; ks < KS; ++ks) {
        float4 v = xp[((size_t)ks * Bq + b) * D4 + tid];
        s.x += v.x; s.y += v.y; s.z += v.z; s.w += v.w;
    }
    s.x = fmaxf(s.x, 0.f); s.y = fmaxf(s.y, 0.f);
    s.z = fmaxf(s.z, 0.f); s.w = fmaxf(s.w, 0.f);

    float4 w = reinterpret_cast<const float4*>(cls_w)[tid];
    float part = s.x * w.x + s.y * w.y + s.z * w.z + s.w * w.w;

    __shared__ float red[10];
#pragma unroll
    for (int o = 16; o > 0; o >>= 1)
        part += __shfl_down_sync(0xffffffffu, part, o);
    if ((tid & 31) == 0) red[tid >> 5] = part;
    __syncthreads();
    if (tid == 0) {
        float tot = 0.f;
#pragma unroll
        for (int i = 0; i < 10; ++i) tot += red[i];
        out[b] = tot + cls_b[0];
    }
}

// ---------------------------------------------------------------------------
extern "C" void kernel_launch(void* const* d_in, const int* in_sizes, int n_in,
                              void* d_out, int out_size)
{
    const float* prev    = (const float*)d_in[0];
    const int*   lengths = (const int*)  d_in[1];
    const float* dense_w = (const float*)d_in[2];
    const float* dense_b = (const float*)d_in[3];
    const float* cls_w   = (const float*)d_in[4];
    const float* cls_b   = (const float*)d_in[5];
    float*       out     = (float*)d_out;

    pool_kernel <<<GPOOL, D4>>>(prev, lengths);
    gemm_kernel <<<KS * NJ, 128>>>(dense_w);
    final_kernel<<<Bq, D4>>>(dense_b, cls_w, cls_b, out);
}

// round 12
// speedup vs baseline: 1.6112x; 1.1764x over previous
#include <cuda_runtime.h>
#include <cuda_bf16.h>

// Problem: B=64, L=1024, D=1280
//   pool_len = lengths + 2
//   emb[b,d]  = mean over l < pool_len of prev[b,l,d]
//   x         = relu(emb @ dense_w + dense_b)        [64,1280]
//   out       = x @ cls_w + cls_b                    [64,1]
//
// Three launches:
//  1) pool_kernel : grid(1024, 2) x 160 thr. Exact task list over valid
//     64-row segments; blockIdx.y picks a D-half (160 float4). 10 blocks/SM
//     resident (occ 78%). Last-arriving block per (b,half) reduces partials
//     and writes embT[k][b] (monotonic counters, replay-safe).
//  2) gemm_kernel : 320 blocks x 256 thr. KS=8 k-splits, tile 64b x 32j x
//     160k, thread 2b x 4j, FFMA2 inner (4 FFMA2 per 2 LDS). Block 0 also
//     initializes out[b] = cls_b.
//  3) final_kernel: grid(64, 5) x 64 thr. k-partial reduce + bias + relu +
//     cls dot, atomicAdd into out.

#define Bq     64
#define Lq     1024
#define Dq     1280
#define D4     320           // float4 per row
#define SEGR   64            // rows per pool segment
#define MAXSEG 16
#define HALFW  160           // float4 per D-half

#define KS     8             // GEMM k-splits
#define KCH    160           // k per split
#define KC     80            // k staged per chunk
#define NJ     40            // j tiles
#define JTW    32            // j tile width

typedef unsigned long long u64;

// scratch (allocation-free: __device__ globals)
__device__ float    g_part [Bq * MAXSEG * Dq];  // pool partials (5.24 MB)
__device__ float    g_embT [Dq * Bq];           // emb transposed [k][b]
__device__ float    g_xpart[KS * Bq * Dq];      // GEMM k-partials (2.62 MB)
__device__ unsigned g_cnt  [Bq * 2];            // per-(b,half) arrival counters

// packed f32x2 FMA (SASS FFMA2)
__device__ __forceinline__ u64 ffma2(u64 a, u64 b, u64 c) {
    u64 d;
    asm("fma.rn.f32x2 %0, %1, %2, %3;" : "=l"(d) : "l"(a), "l"(b), "l"(c));
    return d;
}
__device__ __forceinline__ u64 pack2(float lo, float hi) {
    u64 d;
    asm("mov.b64 %0, {%1, %2};" : "=l"(d) : "f"(lo), "f"(hi));
    return d;
}
__device__ __forceinline__ void unpack2(u64 v, float& lo, float& hi) {
    asm("mov.b64 {%0, %1}, %2;" : "=f"(lo), "=f"(hi) : "l"(v));
}

// ---------------------------------------------------------------------------
// Kernel 1: balanced ragged pool over (segment, D-half) tasks + fused reduce.
// ---------------------------------------------------------------------------
__global__ void __launch_bounds__(HALFW, 10) pool_kernel(
    const float* __restrict__ prev, const int* __restrict__ lengths)
{
    __shared__ int s_pre[Bq + 1];
    __shared__ int s_last;

    const int tid  = threadIdx.x;
    const int half = blockIdx.y;                 // 0 or 1
    const int col  = half * HALFW + tid;         // float4 column 0..319

    if (tid == 0) {
        int acc = 0;
        s_pre[0] = 0;
        for (int b = 0; b < Bq; ++b) {
            int pl = lengths[b] + 2;
            acc += (pl + SEGR - 1) >> 6;
            s_pre[b + 1] = acc;
        }
    }
    __syncthreads();
    const int S = s_pre[Bq];
    const int t = blockIdx.x;
    if (t >= S) return;                          // empty block: retire fast

    // binary search: b with s_pre[b] <= t < s_pre[b+1]
    int lo = 0, hi = Bq;
    while (hi - lo > 1) {
        int m = (lo + hi) >> 1;
        if (s_pre[m] <= t) lo = m; else hi = m;
    }
    const int b    = lo;
    const int seg  = t - s_pre[b];
    const int pl   = lengths[b] + 2;
    const int l0   = seg * SEGR;
    const int n    = min(SEGR, pl - l0);         // >= 1 by construction
    const int nseg = s_pre[b + 1] - s_pre[b];

    float4 a0 = make_float4(0.f, 0.f, 0.f, 0.f);
    float4 a1 = a0, a2 = a0, a3 = a0;

    const float4* __restrict__ p =
        reinterpret_cast<const float4*>(prev) + ((size_t)b * Lq + l0) * D4 + col;
    int l = 0;
    for (; l + 8 <= n; l += 8) {
        float4 v0 = p[(size_t)(l + 0) * D4];
        float4 v1 = p[(size_t)(l + 1) * D4];
        float4 v2 = p[(size_t)(l + 2) * D4];
        float4 v3 = p[(size_t)(l + 3) * D4];
        float4 v4 = p[(size_t)(l + 4) * D4];
        float4 v5 = p[(size_t)(l + 5) * D4];
        float4 v6 = p[(size_t)(l + 6) * D4];
        float4 v7 = p[(size_t)(l + 7) * D4];
        a0.x += v0.x; a0.y += v0.y; a0.z += v0.z; a0.w += v0.w;
        a1.x += v1.x; a1.y += v1.y; a1.z += v1.z; a1.w += v1.w;
        a2.x += v2.x; a2.y += v2.y; a2.z += v2.z; a2.w += v2.w;
        a3.x += v3.x; a3.y += v3.y; a3.z += v3.z; a3.w += v3.w;
        a0.x += v4.x; a0.y += v4.y; a0.z += v4.z; a0.w += v4.w;
        a1.x += v5.x; a1.y += v5.y; a1.z += v5.z; a1.w += v5.w;
        a2.x += v6.x; a2.y += v6.y; a2.z += v6.z; a2.w += v6.w;
        a3.x += v7.x; a3.y += v7.y; a3.z += v7.z; a3.w += v7.w;
    }
    for (; l < n; ++l) {
        float4 v = p[(size_t)l * D4];
        a0.x += v.x; a0.y += v.y; a0.z += v.z; a0.w += v.w;
    }
    float4 s;
    s.x = (a0.x + a1.x) + (a2.x + a3.x);
    s.y = (a0.y + a1.y) + (a2.y + a3.y);
    s.z = (a0.z + a1.z) + (a2.z + a3.z);
    s.w = (a0.w + a1.w) + (a2.w + a3.w);
    reinterpret_cast<float4*>(g_part)[((size_t)b * MAXSEG + seg) * D4 + col] = s;

    // publish partial; last arrival for (b, half) reduces
    __threadfence();
    __syncthreads();
    if (tid == 0) {
        unsigned old = atomicAdd(&g_cnt[b * 2 + half], 1u);
        s_last = (((old + 1u) % (unsigned)nseg) == 0u) ? 1 : 0;
    }
    __syncthreads();
    if (s_last) {
        __threadfence();                         // acquire peers' partials
        const float4* gp = reinterpret_cast<const float4*>(g_part)
                           + (size_t)b * MAXSEG * D4 + col;
        float4 r = make_float4(0.f, 0.f, 0.f, 0.f);
        for (int sg = 0; sg < nseg; ++sg) {
            float4 v = gp[(size_t)sg * D4];
            r.x += v.x; r.y += v.y; r.z += v.z; r.w += v.w;
        }
        const float inv = 1.0f / (float)pl;
        r.x *= inv; r.y *= inv; r.z *= inv; r.w *= inv;
        g_embT[(size_t)(4 * col + 0) * Bq + b] = r.x;
        g_embT[(size_t)(4 * col + 1) * Bq + b] = r.y;
        g_embT[(size_t)(4 * col + 2) * Bq + b] = r.z;
        g_embT[(size_t)(4 * col + 3) * Bq + b] = r.w;
    }
}

// ---------------------------------------------------------------------------
// Kernel 2: k-split GEMM (KS=8), FFMA2. grid 320 = ky*NJ + jx, 256 threads.
// Block tile 64b x 32j x 160k; thread 2b x 4j.
// ---------------------------------------------------------------------------
__global__ void __launch_bounds__(256) gemm_kernel(
    const float* __restrict__ W, const float* __restrict__ cls_b,
    float* __restrict__ out)
{
    __shared__ __align__(16) float sE[KC][Bq];    // 20 KB
    __shared__ __align__(16) float sW[KC][JTW];   // 10 KB

    const int tid = threadIdx.x;
    const int ky  = blockIdx.x / NJ;              // 0..7
    const int jx  = blockIdx.x % NJ;              // 0..39
    const int k0  = ky * KCH;
    const int j0  = jx * JTW;
    const int bg  = tid >> 3;                     // 0..31 -> b = 2bg, 2bg+1
    const int jg  = tid & 7;                      // 0..7  -> j = 4jg..4jg+3

    if (blockIdx.x == 0 && tid < Bq)              // init out for final's atomics
        out[tid] = cls_b[0];

    u64 a00 = 0ull, a01 = 0ull, a10 = 0ull, a11 = 0ull;

    for (int c = 0; c < KCH; c += KC) {
        __syncthreads();
        for (int i = tid; i < KC * Bq; i += 256) {
            int kk = i >> 6;
            int b  = i & 63;
            sE[kk][b] = g_embT[(size_t)(k0 + c + kk) * Bq + b];
        }
        for (int i = tid; i < KC * JTW; i += 256) {
            int kk = i >> 5;
            int jj = i & 31;
            sW[kk][jj] = W[(size_t)(k0 + c + kk) * Dq + j0 + jj];
        }
        __syncthreads();

#pragma unroll 10
        for (int kk = 0; kk < KC; ++kk) {
            float2 e  = *reinterpret_cast<const float2*>(&sE[kk][2 * bg]);
            float4 w  = *reinterpret_cast<const float4*>(&sW[kk][4 * jg]);
            u64 e0  = pack2(e.x, e.x);
            u64 e1  = pack2(e.y, e.y);
            u64 w01 = pack2(w.x, w.y);
            u64 w23 = pack2(w.z, w.w);
            a00 = ffma2(e0, w01, a00);
            a01 = ffma2(e0, w23, a01);
            a10 = ffma2(e1, w01, a10);
            a11 = ffma2(e1, w23, a11);
        }
    }

    float x0, y0, z0, w0f, x1, y1, z1, w1f;
    unpack2(a00, x0, y0); unpack2(a01, z0, w0f);
    unpack2(a10, x1, y1); unpack2(a11, z1, w1f);
    const int b0 = 2 * bg;
    float* dst0 = &g_xpart[((size_t)ky * Bq + b0) * Dq + j0 + 4 * jg];
    *reinterpret_cast<float4*>(dst0)      = make_float4(x0, y0, z0, w0f);
    *reinterpret_cast<float4*>(dst0 + Dq) = make_float4(x1, y1, z1, w1f);
}

// ---------------------------------------------------------------------------
// Kernel 3: reduce k-partials, +bias, relu, dot cls_w, atomicAdd.
// grid(64, 5), 64 threads.
// ---------------------------------------------------------------------------
__global__ void __launch_bounds__(64) final_kernel(
    const float* __restrict__ dense_b,
    const float* __restrict__ cls_w,
    float* __restrict__ out)
{
    const int b   = blockIdx.x;
    const int tid = threadIdx.x;
    const int d4  = blockIdx.y * 64 + tid;        // 0..319
    const float4* xp = reinterpret_cast<const float4*>(g_xpart);

    float4 s = reinterpret_cast<const float4*>(dense_b)[d4];
#pragma unroll
    for (int ks = 0; ks < KS; ++ks) {
        float4 v = xp[((size_t)ks * Bq + b) * D4 + d4];
        s.x += v.x; s.y += v.y; s.z += v.z; s.w += v.w;
    }
    s.x = fmaxf(s.x, 0.f); s.y = fmaxf(s.y, 0.f);
    s.z = fmaxf(s.z, 0.f); s.w = fmaxf(s.w, 0.f);

    float4 w = reinterpret_cast<const float4*>(cls_w)[d4];
    float part = s.x * w.x + s.y * w.y + s.z * w.z + s.w * w.w;

#pragma unroll
    for (int o = 16; o > 0; o >>= 1)
        part += __shfl_down_sync(0xffffffffu, part, o);
    if ((tid & 31) == 0)
        atomicAdd(&out[b], part);                 // 10 adds per b total
}

// ---------------------------------------------------------------------------
extern "C" void kernel_launch(void* const* d_in, const int* in_sizes, int n_in,
                              void* d_out, int out_size)
{
    const float* prev    = (const float*)d_in[0];
    const int*   lengths = (const int*)  d_in[1];
    const float* dense_w = (const float*)d_in[2];
    const float* dense_b = (const float*)d_in[3];
    const float* cls_w   = (const float*)d_in[4];
    const float* cls_b   = (const float*)d_in[5];
    float*       out     = (float*)d_out;

    pool_kernel <<<dim3(1024, 2), HALFW>>>(prev, lengths);
    gemm_kernel <<<KS * NJ, 256>>>(dense_w, cls_b, out);
    final_kernel<<<dim3(Bq, 5), 64>>>(dense_b, cls_w, out);
}